// round 9
// baseline (speedup 1.0000x reference)
#include <cuda_runtime.h>
#include <cuda_bf16.h>
#include <cstdint>

// ---------------- problem constants ----------------
#define B_IMG 75
#define N_CLS 5
#define C_DIM 640
#define HW    441
#define HPAD  448           // 3 full 128-tiles + one 64-tile
#define NK    10            // K chunks of 64
#define NEG_INF (-1e30f)

// ---------------- device scratch ----------------
__device__ __align__(256) __nv_bfloat16 g_qbf[(size_t)B_IMG * HPAD * C_DIM];
__device__ __align__(256) __nv_bfloat16 g_sbf[(size_t)N_CLS * HPAD * C_DIM];
__device__ float g_nsq[(size_t)80 * HPAD * 10];     // norm partials [img][hw][c_t]
__device__ float g_qn_inv[B_IMG * HW];
__device__ float g_sn_inv[N_CLS * HW];
// per-CTA top-3 partials: [(b*5+n)*4+mt][128 rows][qt*3+c]
__device__ float g_top3[(size_t)B_IMG * N_CLS * 4 * 128 * 12];

// ---------------- smem layout (gemm kernel) ----------------
#define STG_BYTES 32768                 // A ≤16KB + B ≤16KB, SW128-swizzled
#define QINV_OFF  (3 * STG_BYTES)       // 98304, 128 floats
#define CAND_OFF  (QINV_OFF + 512)      // 98816, 128*3 floats
#define SMEM_DYN  (CAND_OFF + 1536)     // 100352

// ---------------- PTX helpers (arch-generic, sm_80+) ----------------
__device__ __forceinline__ uint32_t smem_u32(const void* p) {
    uint32_t a;
    asm("{ .reg .u64 t; cvta.to.shared.u64 t, %1; cvt.u32.u64 %0, t; }" : "=r"(a) : "l"(p));
    return a;
}
__device__ __forceinline__ void cpasync16(uint32_t saddr, const void* g) {
    asm volatile("cp.async.cg.shared.global [%0], [%1], 16;" :: "r"(saddr), "l"(g));
}
__device__ __forceinline__ void cp_commit() { asm volatile("cp.async.commit_group;" ::: "memory"); }

#define LDSM_X4(r0, r1, r2, r3, addr) \
    asm volatile("ldmatrix.sync.aligned.m8n8.x4.shared.b16 {%0,%1,%2,%3}, [%4];" \
                 : "=r"(r0), "=r"(r1), "=r"(r2), "=r"(r3) : "r"(addr))

#define MMA16816(c, a, bb) \
    asm volatile("mma.sync.aligned.m16n8k16.row.col.f32.bf16.bf16.f32 " \
                 "{%0,%1,%2,%3}, {%4,%5,%6,%7}, {%8,%9}, {%0,%1,%2,%3};" \
                 : "+f"((c)[0]), "+f"((c)[1]), "+f"((c)[2]), "+f"((c)[3]) \
                 : "r"((a)[0]), "r"((a)[1]), "r"((a)[2]), "r"((a)[3]), \
                   "r"((bb)[0]), "r"((bb)[1]))

__device__ __forceinline__ void insert3(float& t0, float& t1, float& t2, float v) {
    if (v > t2) {
        if (v > t1) {
            t2 = t1;
            if (v > t0) { t1 = t0; t0 = v; }
            else        { t1 = v; }
        } else {
            t2 = v;
        }
    }
}

// ---------------------------------------------------------------------------
// 1) transpose + convert fp32 [img][C][HW] -> bf16 [img][448][C] (zero-padded)
//    and emit fp32 norm partials (sum of squares per 64-channel block).
// ---------------------------------------------------------------------------
__global__ __launch_bounds__(256) void transpose_bf16_kernel(
        const float* __restrict__ q, const float* __restrict__ S) {
    const int hw_t = blockIdx.x;   // 0..6
    const int c_t  = blockIdx.y;   // 0..9
    const int img  = blockIdx.z;   // 0..79

    const float* src;
    __nv_bfloat16* dst;
    if (img < B_IMG) {
        src = q + (size_t)img * C_DIM * HW;
        dst = g_qbf + (size_t)img * HPAD * C_DIM;
    } else {
        src = S + (size_t)(img - B_IMG) * C_DIM * HW;
        dst = g_sbf + (size_t)(img - B_IMG) * HPAD * C_DIM;
    }
    const int hw0 = hw_t * 64;
    const int c0  = c_t * 64;

    __shared__ float ts[64][65];
    const int tid = threadIdx.x;

    #pragma unroll
    for (int i = 0; i < 16; ++i) {
        int idx = i * 256 + tid;
        int cl = idx >> 6, hl = idx & 63;
        int hw = hw0 + hl;
        ts[hl][cl] = (hw < HW) ? src[(size_t)(c0 + cl) * HW + hw] : 0.f;
    }
    __syncthreads();

    if (tid < 64) {
        float s = 0.f;
        #pragma unroll 8
        for (int cl = 0; cl < 64; ++cl) { float v = ts[tid][cl]; s = fmaf(v, v, s); }
        g_nsq[((size_t)img * HPAD + hw0 + tid) * 10 + c_t] = s;
    }

    #pragma unroll
    for (int i = 0; i < 2; ++i) {
        int slot = i * 256 + tid;
        int hl = slot >> 3, ch = slot & 7;
        uint32_t w[4];
        #pragma unroll
        for (int j = 0; j < 4; ++j) {
            __nv_bfloat162 p = __floats2bfloat162_rn(ts[hl][ch * 8 + 2 * j],
                                                     ts[hl][ch * 8 + 2 * j + 1]);
            w[j] = *reinterpret_cast<uint32_t*>(&p);
        }
        *reinterpret_cast<uint4*>(dst + (size_t)(hw0 + hl) * C_DIM + c0 + ch * 8) =
            make_uint4(w[0], w[1], w[2], w[3]);
    }
}

// ---------------------------------------------------------------------------
// 2) finish norms: sum 10 partials (fixed order), rsqrt
// ---------------------------------------------------------------------------
__global__ void norm_finish_kernel() {
    int idx = blockIdx.x * blockDim.x + threadIdx.x;   // over 80*448
    if (idx >= 80 * HPAD) return;
    int img = idx / HPAD, hw = idx - img * HPAD;
    if (hw >= HW) return;
    const float* p = &g_nsq[(size_t)idx * 10];
    float s = 0.f;
    #pragma unroll
    for (int c = 0; c < 10; ++c) s += p[c];
    float r = rsqrtf(s);
    if (img < B_IMG) g_qn_inv[img * HW + hw] = r;
    else             g_sn_inv[(img - B_IMG) * HW + hw] = r;
}

// ---------------------------------------------------------------------------
// 3) HMMA GEMM + fused top-3, variable tile: (FM?128:64) x (FN?128:64) x 640.
//    3-stage cp.async ring, 1 sync per K-stage, SW128 XOR swizzle,
//    kk-software-pipelined ldmatrix fragment loads.
// ---------------------------------------------------------------------------
template <int RA, int RB>
__device__ __forceinline__ void fill_stage(
        uint32_t sbase, const __nv_bfloat16* Ag, const __nv_bfloat16* Bg,
        int k0, int tid) {
    constexpr int ACH = RA * 8;
    constexpr int TOT = (RA + RB) * 8;
    #pragma unroll
    for (int it = 0; it < TOT / 256; ++it) {
        int idx = it * 256 + tid;
        if (idx < ACH) {
            int row = idx >> 3, ch = idx & 7;
            uint32_t off = (uint32_t)(row * 128) +
                           (uint32_t)((ch * 16) ^ ((row & 7) << 4));
            cpasync16(sbase + off, Ag + (size_t)row * C_DIM + k0 + ch * 8);
        } else {
            int i2 = idx - ACH;
            int row = i2 >> 3, ch = i2 & 7;
            uint32_t off = (uint32_t)(row * 128) +
                           (uint32_t)((ch * 16) ^ ((row & 7) << 4));
            cpasync16(sbase + (uint32_t)(RA * 128) + off,
                      Bg + (size_t)row * C_DIM + k0 + ch * 8);
        }
    }
}

template <bool FM, bool FN>
__device__ __forceinline__ void gemm_body(char* sm, int mt, int qt, int n, int b) {
    constexpr int RA  = FM ? 128 : 64;
    constexpr int RB  = FN ? 128 : 64;
    constexpr int FMC = FM ? 2 : 1;       // 16-row fragments per warp (M)
    constexpr int NFC = FN ? 8 : 4;       // 8-col fragments per warp (N)
    constexpr int WMS = FM ? 32 : 16;     // warp M span
    constexpr int WNS = FN ? 64 : 32;     // warp N span

    const uint32_t sb = smem_u32(sm);
    const int tid  = threadIdx.x;
    const int lane = tid & 31;
    const int wid  = tid >> 5;
    const int wm   = wid >> 1;            // 0..3 (M)
    const int wn   = wid & 1;             // 0..1 (N)

    float* qinvp = reinterpret_cast<float*>(sm + QINV_OFF);
    float* candp = reinterpret_cast<float*>(sm + CAND_OFF);

    const __nv_bfloat16* Ag = g_sbf + ((size_t)n * HPAD + (size_t)mt * 128) * C_DIM;
    const __nv_bfloat16* Bg = g_qbf + ((size_t)b * HPAD + (size_t)qt * 128) * C_DIM;

    if (tid < RB) {
        int col = qt * 128 + tid;
        qinvp[tid] = (col < HW) ? g_qn_inv[b * HW + col] : 0.f;
    }

    fill_stage<RA, RB>(sb, Ag, Bg, 0, tid);              cp_commit();
    fill_stage<RA, RB>(sb + STG_BYTES, Ag, Bg, 64, tid); cp_commit();

    float acc[FMC][NFC][4];
    #pragma unroll
    for (int fm = 0; fm < FMC; ++fm)
        #pragma unroll
        for (int nf = 0; nf < NFC; ++nf)
            #pragma unroll
            for (int r = 0; r < 4; ++r) acc[fm][nf][r] = 0.f;

    // lane-fixed LDSM address pieces
    const int a_row = wm * WMS + (lane & 15);
    const uint32_t a_rowoff = (uint32_t)a_row * 128;
    const uint32_t a_xor = (uint32_t)(a_row & 7) << 4;
    const uint32_t a_sub = (uint32_t)(lane >> 4) << 4;
    const int b_row = wn * WNS + (lane & 7) + ((lane >> 4) << 3);
    const uint32_t b_rowoff = (uint32_t)b_row * 128;
    const uint32_t b_xor = (uint32_t)(b_row & 7) << 4;
    const uint32_t b_sub = (uint32_t)((lane >> 3) & 1) << 4;

    #pragma unroll 1
    for (int s = 0; s < NK; ++s) {
        asm volatile("cp.async.wait_group 1;" ::: "memory");
        __syncthreads();

        const uint32_t ab = sb + (uint32_t)(s % 3) * STG_BYTES;
        const uint32_t bb = ab + (uint32_t)(RA * 128);

        // double-buffered fragment registers, pipelined over kk
        uint32_t aF[2][FMC][4];
        uint32_t bF[2][NFC][2];

        // prefetch kk = 0 fragments (LDS latency overlaps the fill issue below)
        #pragma unroll
        for (int fm = 0; fm < FMC; ++fm)
            LDSM_X4(aF[0][fm][0], aF[0][fm][1], aF[0][fm][2], aF[0][fm][3],
                    ab + a_rowoff + (uint32_t)fm * 2048 + (a_sub ^ a_xor));
        #pragma unroll
        for (int nf2 = 0; nf2 < NFC / 2; ++nf2) {
            uint32_t r0, r1, r2, r3;
            LDSM_X4(r0, r1, r2, r3,
                    bb + b_rowoff + (uint32_t)nf2 * 2048 + (b_sub ^ b_xor));
            bF[0][nf2 * 2][0] = r0;     bF[0][nf2 * 2][1] = r1;
            bF[0][nf2 * 2 + 1][0] = r2; bF[0][nf2 * 2 + 1][1] = r3;
        }

        if (s + 2 < NK)
            fill_stage<RA, RB>(sb + (uint32_t)((s + 2) % 3) * STG_BYTES,
                               Ag, Bg, (s + 2) * 64, tid);
        cp_commit();

        #pragma unroll
        for (int kk = 0; kk < 4; ++kk) {
            const int cur = kk & 1, nxt = cur ^ 1;
            if (kk < 3) {
                const uint32_t koff = (uint32_t)((kk + 1) * 32);
                #pragma unroll
                for (int fm = 0; fm < FMC; ++fm)
                    LDSM_X4(aF[nxt][fm][0], aF[nxt][fm][1],
                            aF[nxt][fm][2], aF[nxt][fm][3],
                            ab + a_rowoff + (uint32_t)fm * 2048 +
                            ((koff + a_sub) ^ a_xor));
                #pragma unroll
                for (int nf2 = 0; nf2 < NFC / 2; ++nf2) {
                    uint32_t r0, r1, r2, r3;
                    LDSM_X4(r0, r1, r2, r3,
                            bb + b_rowoff + (uint32_t)nf2 * 2048 +
                            ((koff + b_sub) ^ b_xor));
                    bF[nxt][nf2 * 2][0] = r0;     bF[nxt][nf2 * 2][1] = r1;
                    bF[nxt][nf2 * 2 + 1][0] = r2; bF[nxt][nf2 * 2 + 1][1] = r3;
                }
            }
            #pragma unroll
            for (int fm = 0; fm < FMC; ++fm)
                #pragma unroll
                for (int nf = 0; nf < NFC; ++nf)
                    MMA16816(acc[fm][nf], aF[cur][fm], bF[cur][nf]);
        }
    }

    // ---- epilogue: scale by qinv, per-thread top-3 ----
    const int col_l = wn * WNS + (lane & 3) * 2;
    float t3[FMC][2][3];
    #pragma unroll
    for (int fm = 0; fm < FMC; ++fm)
        #pragma unroll
        for (int h = 0; h < 2; ++h) {
            t3[fm][h][0] = NEG_INF; t3[fm][h][1] = NEG_INF; t3[fm][h][2] = NEG_INF;
        }
    #pragma unroll
    for (int nf = 0; nf < NFC; ++nf)
        #pragma unroll
        for (int dc = 0; dc < 2; ++dc) {
            // FULLN tiles (qt<3): all cols < 441, no guard needed
            bool ok = FN || (qt * 128 + col_l + nf * 8 + dc < HW);
            if (ok) {
                float qi = qinvp[col_l + nf * 8 + dc];
                #pragma unroll
                for (int fm = 0; fm < FMC; ++fm)
                    #pragma unroll
                    for (int h = 0; h < 2; ++h) {
                        float v = acc[fm][nf][h * 2 + dc] * qi;
                        insert3(t3[fm][h][0], t3[fm][h][1], t3[fm][h][2], v);
                    }
            }
        }

    // merge across the 4 lanes (lane&3) holding the same row
    #pragma unroll
    for (int o = 1; o <= 2; o <<= 1) {
        #pragma unroll
        for (int fm = 0; fm < FMC; ++fm)
            #pragma unroll
            for (int h = 0; h < 2; ++h) {
                float r0 = __shfl_xor_sync(0xffffffffu, t3[fm][h][0], o);
                float r1 = __shfl_xor_sync(0xffffffffu, t3[fm][h][1], o);
                float r2 = __shfl_xor_sync(0xffffffffu, t3[fm][h][2], o);
                insert3(t3[fm][h][0], t3[fm][h][1], t3[fm][h][2], r0);
                insert3(t3[fm][h][0], t3[fm][h][1], t3[fm][h][2], r1);
                insert3(t3[fm][h][0], t3[fm][h][1], t3[fm][h][2], r2);
            }
    }

    // cross-wn merge via smem, then one writer per row
    __syncthreads();
    if (wn == 1 && (lane & 3) == 0) {
        #pragma unroll
        for (int fm = 0; fm < FMC; ++fm)
            #pragma unroll
            for (int h = 0; h < 2; ++h) {
                int m = wm * WMS + fm * 16 + h * 8 + (lane >> 2);
                candp[m * 3 + 0] = t3[fm][h][0];
                candp[m * 3 + 1] = t3[fm][h][1];
                candp[m * 3 + 2] = t3[fm][h][2];
            }
    }
    __syncthreads();
    if (wn == 0 && (lane & 3) == 0) {
        #pragma unroll
        for (int fm = 0; fm < FMC; ++fm)
            #pragma unroll
            for (int h = 0; h < 2; ++h) {
                int m = wm * WMS + fm * 16 + h * 8 + (lane >> 2);
                insert3(t3[fm][h][0], t3[fm][h][1], t3[fm][h][2], candp[m * 3 + 0]);
                insert3(t3[fm][h][0], t3[fm][h][1], t3[fm][h][2], candp[m * 3 + 1]);
                insert3(t3[fm][h][0], t3[fm][h][1], t3[fm][h][2], candp[m * 3 + 2]);
                float* g = &g_top3[((((size_t)(b * N_CLS + n) * 4 + mt) * 128 + m) * 12)
                                   + qt * 3];
                g[0] = t3[fm][h][0]; g[1] = t3[fm][h][1]; g[2] = t3[fm][h][2];
            }
    }
}

__global__ __launch_bounds__(256, 2) void gemm_top3_mma() {
    extern __shared__ char sm[];
    const int mt = blockIdx.x & 3, qt = blockIdx.x >> 2;
    const int n  = blockIdx.y,     b  = blockIdx.z;
    if (mt < 3) {
        if (qt < 3) gemm_body<true,  true >(sm, mt, qt, n, b);
        else        gemm_body<true,  false>(sm, mt, qt, n, b);
    } else {
        if (qt < 3) gemm_body<false, true >(sm, mt, qt, n, b);
        else        gemm_body<false, false>(sm, mt, qt, n, b);
    }
}

// ---------------------------------------------------------------------------
// 4) merge: fold 4 qt-partials per support row, sum * sn_inv, block-reduce.
// ---------------------------------------------------------------------------
__global__ __launch_bounds__(512) void merge_kernel(float* __restrict__ out) {
    const int n = blockIdx.x, b = blockIdx.y;
    const int m = threadIdx.x;
    __shared__ float red[512];
    float part = 0.f;
    if (m < HW) {
        const float* p = &g_top3[(((size_t)(b * N_CLS + n) * 4 + (m >> 7)) * 128
                                  + (m & 127)) * 12];
        float t0 = NEG_INF, t1 = NEG_INF, t2 = NEG_INF;
        #pragma unroll
        for (int c = 0; c < 12; ++c) insert3(t0, t1, t2, p[c]);
        part = (t0 + t1 + t2) * g_sn_inv[n * HW + m];
    }
    red[m] = part;
    __syncthreads();
    #pragma unroll
    for (int s = 256; s > 32; s >>= 1) {
        if (m < s) red[m] += red[m + s];
        __syncthreads();
    }
    if (m < 32) {
        float v = red[m] + red[m + 32];
        #pragma unroll
        for (int o = 16; o > 0; o >>= 1)
            v += __shfl_down_sync(0xffffffffu, v, o);
        if (m == 0) out[b * N_CLS + n] = v;
    }
}

extern "C" void kernel_launch(void* const* d_in, const int* in_sizes, int n_in,
                              void* d_out, int out_size) {
    (void)in_sizes; (void)n_in; (void)out_size;
    const float* q = (const float*)d_in[0];
    const float* S = (const float*)d_in[1];
    float* out = (float*)d_out;

    static int smem_set = 0;  // idempotent attribute, set once
    if (!smem_set) {
        cudaFuncSetAttribute(gemm_top3_mma,
                             cudaFuncAttributeMaxDynamicSharedMemorySize, SMEM_DYN);
        smem_set = 1;
    }

    transpose_bf16_kernel<<<dim3(7, 10, 80), 256>>>(q, S);
    norm_finish_kernel<<<(80 * HPAD + 255) / 256, 256>>>();
    gemm_top3_mma<<<dim3(16, N_CLS, B_IMG), 256, SMEM_DYN>>>();
    merge_kernel<<<dim3(N_CLS, B_IMG), 512>>>(out);
}